// round 8
// baseline (speedup 1.0000x reference)
#include <cuda_runtime.h>
#include <cuda_bf16.h>
#include <stdint.h>
#include <cstdint>
#include <math.h>

#define DM   1024      // d_model
#define VOC  50264
#define DS   16        // d_state
#define DI   2048      // d_inner
#define DTR  64        // dt_rank
#define LSEQ 2048
#define XDBL 96        // dt_rank + 2*d_state
#define KSPL 16        // split-K factor for x_proj
#define PSTRIDE (LSEQ * XDBL)

// ---------------- scratch (device globals; no allocation allowed) ----------------
__device__ float g_x[LSEQ * DM];        // residual stream
__device__ float g_xn[LSEQ * DM];       // rmsnorm output
__device__ float g_xr[LSEQ * 2 * DI];   // in_proj output (x | res)
__device__ float g_xp[LSEQ * DI];       // post conv+silu
__device__ float g_xdbl[LSEQ * XDBL];   // x_proj output (dt | B | C)
__device__ float g_delta[LSEQ * DI];    // softplus(dt_proj)
__device__ float g_y[LSEQ * DI];        // scan output (gated in-scan)
__device__ float g_part[KSPL * PSTRIDE];  // split-K partials for x_proj

__device__ __forceinline__ float siluf(float x) { return x / (1.0f + __expf(-x)); }
__device__ __forceinline__ float softplusf(float x) {
    return (x > 20.0f) ? x : log1pf(expf(x));
}
__device__ __forceinline__ unsigned f2tf32(float f) {
    unsigned r; asm("cvt.rna.tf32.f32 %0, %1;" : "=r"(r) : "f"(f)); return r;
}
__device__ __forceinline__ void mma_tf32(float c[4], const unsigned a[4], const unsigned b[2]) {
    asm volatile(
        "mma.sync.aligned.m16n8k8.row.col.f32.tf32.tf32.f32 "
        "{%0,%1,%2,%3}, {%4,%5,%6,%7}, {%8,%9}, {%0,%1,%2,%3};"
        : "+f"(c[0]), "+f"(c[1]), "+f"(c[2]), "+f"(c[3])
        : "r"(a[0]), "r"(a[1]), "r"(a[2]), "r"(a[3]), "r"(b[0]), "r"(b[1]));
}

// ---------------- embedding gather ----------------
__global__ void embed_kernel(const int* __restrict__ ids, const float* __restrict__ emb) {
    int i = blockIdx.x * blockDim.x + threadIdx.x;
    int l = i >> 10, c = i & (DM - 1);
    g_x[i] = emb[(long)ids[l] * DM + c];
}

// ---------------- rmsnorm: one block per row ----------------
__global__ void rmsnorm_kernel(const float* __restrict__ x, const float* __restrict__ w,
                               float* __restrict__ out) {
    int row = blockIdx.x;
    const float* xr = x + row * DM;
    float s = 0.0f;
    for (int c = threadIdx.x; c < DM; c += blockDim.x) { float v = xr[c]; s += v * v; }
    __shared__ float red[32];
    #pragma unroll
    for (int o = 16; o; o >>= 1) s += __shfl_xor_sync(~0u, s, o);
    if ((threadIdx.x & 31) == 0) red[threadIdx.x >> 5] = s;
    __syncthreads();
    if (threadIdx.x < 32) {
        float v = (threadIdx.x < (blockDim.x >> 5)) ? red[threadIdx.x] : 0.0f;
        #pragma unroll
        for (int o = 16; o; o >>= 1) v += __shfl_xor_sync(~0u, v, o);
        if (threadIdx.x == 0) red[0] = v;
    }
    __syncthreads();
    float inv = rsqrtf(red[0] / (float)DM + 1e-5f);
    for (int c = threadIdx.x; c < DM; c += blockDim.x)
        out[row * DM + c] = xr[c] * inv * w[c];
}

// ---------------- causal depthwise conv1d (k=4) + bias + silu ----------------
__global__ void conv_silu_kernel(const float* __restrict__ cw, const float* __restrict__ cb) {
    int i = blockIdx.x * blockDim.x + threadIdx.x;
    int l = i >> 11, d = i & (DI - 1);
    float acc = cb[d];
    #pragma unroll
    for (int t = 0; t < 4; t++) {
        int ls = l - 3 + t;
        if (ls >= 0) acc = fmaf(cw[d * 4 + t], g_xr[ls * (2 * DI) + d], acc);
    }
    g_xp[i] = siluf(acc);
}

// ---------------- selective scan (gate fused): one thread per (d, n) ----------------
__global__ void scan_kernel(const float* __restrict__ A_log, const float* __restrict__ Dp) {
    int t = blockIdx.x * blockDim.x + threadIdx.x;
    int d = t >> 4, n = t & 15;
    float A_dn = -expf(A_log[d * DS + n]);
    float Dv = Dp[d];
    float h = 0.0f;
    for (int l = 0; l < LSEQ; l++) {
        float dl = g_delta[l * DI + d];
        float u  = g_xp[l * DI + d];
        float Bv = g_xdbl[l * XDBL + DTR + n];
        float Cv = g_xdbl[l * XDBL + DTR + DS + n];
        float dA = __expf(dl * A_dn);
        h = fmaf(dA, h, dl * u * Bv);
        float py = h * Cv;
        #pragma unroll
        for (int o = 8; o; o >>= 1) py += __shfl_xor_sync(~0u, py, o);
        if (n == 0) {
            float res = g_xr[l * (2 * DI) + DI + d];
            g_y[l * DI + d] = (py + u * Dv) * siluf(res);
        }
    }
}

// ================= TF32 mma.sync NT GEMM, 128x128 (proven round-4 kernel) =================
// EPI: 0 = none, 2 = +residual.
template <int EPI>
__global__ __launch_bounds__(256, 2)
void mma_nt(const float* __restrict__ A, int lda,
            const float* __restrict__ B, int ldb,
            float* __restrict__ C, int ldc,
            int N, int K, const float* __restrict__ resid) {
    __shared__ unsigned sA[2][2][8][32][4];
    __shared__ unsigned sB[2][2][16][32][2];

    const int tid  = threadIdx.x;
    const int lane = tid & 31;
    const int warp = tid >> 5;
    const int wm = warp & 1;
    const int wn = warp >> 1;
    const int rowBase = blockIdx.y * 128;
    const int colBase = blockIdx.x * 128;

    const int r0  = tid >> 2;
    const int kq  = tid & 3;
    const float* Arow0 = A + (long)(rowBase + r0) * lda + kq * 4;
    const float* Arow1 = A + (long)(rowBase + r0 + 64) * lda + kq * 4;
    const int nIdx0 = colBase + r0;
    const int nIdx1 = colBase + r0 + 64;
    const float* Brow0 = B + (long)nIdx0 * ldb + kq * 4;
    const float* Brow1 = B + (long)nIdx1 * ldb + kq * 4;
    const bool bv0 = nIdx0 < N;
    const bool bv1 = nIdx1 < N;

    float acc[4][4][4];
    #pragma unroll
    for (int i = 0; i < 4; i++)
        #pragma unroll
        for (int j = 0; j < 4; j++)
            #pragma unroll
            for (int q = 0; q < 4; q++) acc[i][j][q] = 0.0f;

    float4 ra[2], rb[2];
    auto ldg = [&](int k0) {
        ra[0] = *(const float4*)(Arow0 + k0);
        ra[1] = *(const float4*)(Arow1 + k0);
        rb[0] = bv0 ? *(const float4*)(Brow0 + k0) : make_float4(0.f,0.f,0.f,0.f);
        rb[1] = bv1 ? *(const float4*)(Brow1 + k0) : make_float4(0.f,0.f,0.f,0.f);
    };
    auto sts = [&](int st) {
        const int k8 = kq >> 1;
        #pragma unroll
        for (int h = 0; h < 2; h++) {
            int row = r0 + h * 64;
            unsigned* pa = &sA[st][k8][row >> 4][(row & 7) * 4][(kq & 1) * 2 + ((row >> 3) & 1)];
            pa[0]  = f2tf32(ra[h].x);
            pa[4]  = f2tf32(ra[h].y);
            pa[8]  = f2tf32(ra[h].z);
            pa[12] = f2tf32(ra[h].w);
            unsigned* pb = &sB[st][k8][row >> 3][(row & 7) * 4][kq & 1];
            pb[0] = f2tf32(rb[h].x);
            pb[2] = f2tf32(rb[h].y);
            pb[4] = f2tf32(rb[h].z);
            pb[6] = f2tf32(rb[h].w);
        }
    };
    auto compute = [&](int st) {
        #pragma unroll
        for (int ks = 0; ks < 2; ks++) {
            unsigned af[4][4];
            unsigned bf[4][2];
            #pragma unroll
            for (int i = 0; i < 4; i++) {
                uint4 v = *(const uint4*)&sA[st][ks][wm * 4 + i][lane][0];
                af[i][0] = v.x; af[i][1] = v.y; af[i][2] = v.z; af[i][3] = v.w;
            }
            #pragma unroll
            for (int j = 0; j < 4; j++) {
                uint2 v = *(const uint2*)&sB[st][ks][wn * 4 + j][lane][0];
                bf[j][0] = v.x; bf[j][1] = v.y;
            }
            #pragma unroll
            for (int i = 0; i < 4; i++)
                #pragma unroll
                for (int j = 0; j < 4; j++)
                    mma_tf32(acc[i][j], af[i], bf[j]);
        }
    };

    ldg(0);
    sts(0);
    __syncthreads();
    int buf = 0;
    for (int k0 = 16; k0 < K; k0 += 16) {
        ldg(k0);
        compute(buf);
        sts(buf ^ 1);
        __syncthreads();
        buf ^= 1;
    }
    compute(buf);

    const int g   = lane >> 2;
    const int tig = lane & 3;
    #pragma unroll
    for (int i = 0; i < 4; i++) {
        const long row0 = rowBase + wm * 64 + i * 16 + g;
        #pragma unroll
        for (int j = 0; j < 4; j++) {
            const int col = colBase + wn * 32 + j * 8 + tig * 2;
            if (col < N) {
                float2 v01 = make_float2(acc[i][j][0], acc[i][j][1]);
                float2 v23 = make_float2(acc[i][j][2], acc[i][j][3]);
                if (EPI == 2) {
                    float2 t0 = *(const float2*)&resid[row0 * ldc + col];
                    float2 t1 = *(const float2*)&resid[(row0 + 8) * ldc + col];
                    v01.x += t0.x; v01.y += t0.y;
                    v23.x += t1.x; v23.y += t1.y;
                }
                *(float2*)&C[row0 * ldc + col]       = v01;
                *(float2*)&C[(row0 + 8) * ldc + col] = v23;
            }
        }
    }
}

// ================= TF32 mma.sync NT GEMM, 128x256 (warp tile 64x64) =================
// Higher MMA:LDS ratio variant for the big-N GEMMs (logits, in_proj). EPI none.
__global__ __launch_bounds__(256, 1)
void mma_big(const float* __restrict__ A, int lda,
             const float* __restrict__ B, int ldb,
             float* __restrict__ C, int ldc,
             int N, int K) {
    __shared__ unsigned sA[2][2][8][32][4];    // 16 KB
    __shared__ unsigned sB[2][2][32][32][2];   // 32 KB

    const int tid  = threadIdx.x;
    const int lane = tid & 31;
    const int warp = tid >> 5;
    const int wm = warp & 1;      // 2 strips of 64 rows
    const int wn = warp >> 1;     // 4 strips of 64 cols
    const int rowBase = blockIdx.y * 128;
    const int colBase = blockIdx.x * 256;

    const int r0  = tid >> 2;     // 0..63
    const int kq  = tid & 3;
    const float* Arow0 = A + (long)(rowBase + r0) * lda + kq * 4;
    const float* Arow1 = A + (long)(rowBase + r0 + 64) * lda + kq * 4;
    const float* Brow[4];
    bool bv[4];
    #pragma unroll
    for (int h = 0; h < 4; h++) {
        int n = colBase + r0 + h * 64;
        bv[h] = n < N;
        Brow[h] = B + (long)n * ldb + kq * 4;
    }

    float acc[4][8][4];
    #pragma unroll
    for (int i = 0; i < 4; i++)
        #pragma unroll
        for (int j = 0; j < 8; j++)
            #pragma unroll
            for (int q = 0; q < 4; q++) acc[i][j][q] = 0.0f;

    float4 ra[2], rb[4];
    auto ldg = [&](int k0) {
        ra[0] = *(const float4*)(Arow0 + k0);
        ra[1] = *(const float4*)(Arow1 + k0);
        #pragma unroll
        for (int h = 0; h < 4; h++)
            rb[h] = bv[h] ? *(const float4*)(Brow[h] + k0) : make_float4(0.f,0.f,0.f,0.f);
    };
    auto sts = [&](int st) {
        const int k8 = kq >> 1;
        #pragma unroll
        for (int h = 0; h < 2; h++) {
            int row = r0 + h * 64;
            unsigned* pa = &sA[st][k8][row >> 4][(row & 7) * 4][(kq & 1) * 2 + ((row >> 3) & 1)];
            pa[0]  = f2tf32(ra[h].x);
            pa[4]  = f2tf32(ra[h].y);
            pa[8]  = f2tf32(ra[h].z);
            pa[12] = f2tf32(ra[h].w);
        }
        #pragma unroll
        for (int h = 0; h < 4; h++) {
            int row = r0 + h * 64;
            unsigned* pb = &sB[st][k8][row >> 3][(row & 7) * 4][kq & 1];
            pb[0] = f2tf32(rb[h].x);
            pb[2] = f2tf32(rb[h].y);
            pb[4] = f2tf32(rb[h].z);
            pb[6] = f2tf32(rb[h].w);
        }
    };
    auto compute = [&](int st) {
        #pragma unroll
        for (int ks = 0; ks < 2; ks++) {
            unsigned af[4][4];
            unsigned bf[8][2];
            #pragma unroll
            for (int i = 0; i < 4; i++) {
                uint4 v = *(const uint4*)&sA[st][ks][wm * 4 + i][lane][0];
                af[i][0] = v.x; af[i][1] = v.y; af[i][2] = v.z; af[i][3] = v.w;
            }
            #pragma unroll
            for (int j = 0; j < 8; j++) {
                uint2 v = *(const uint2*)&sB[st][ks][wn * 8 + j][lane][0];
                bf[j][0] = v.x; bf[j][1] = v.y;
            }
            #pragma unroll
            for (int i = 0; i < 4; i++)
                #pragma unroll
                for (int j = 0; j < 8; j++)
                    mma_tf32(acc[i][j], af[i], bf[j]);
        }
    };

    ldg(0);
    sts(0);
    __syncthreads();
    int buf = 0;
    for (int k0 = 16; k0 < K; k0 += 16) {
        ldg(k0);
        compute(buf);
        sts(buf ^ 1);
        __syncthreads();
        buf ^= 1;
    }
    compute(buf);

    const int g   = lane >> 2;
    const int tig = lane & 3;
    #pragma unroll
    for (int i = 0; i < 4; i++) {
        const long row0 = rowBase + wm * 64 + i * 16 + g;
        #pragma unroll
        for (int j = 0; j < 8; j++) {
            const int col = colBase + wn * 64 + j * 8 + tig * 2;
            if (col < N) {
                *(float2*)&C[row0 * ldc + col]       = make_float2(acc[i][j][0], acc[i][j][1]);
                *(float2*)&C[(row0 + 8) * ldc + col] = make_float2(acc[i][j][2], acc[i][j][3]);
            }
        }
    }
}

// ---------------- fp32 NT SGEMM (small/precision-critical GEMMs) ----------------
// EPI: 0 = none, 1 = +bias then softplus, 3 = split-K partial (blockIdx.z = chunk)
template <int EPI>
__global__ __launch_bounds__(256, 2)
void sgemm_nt(const float* __restrict__ A, int lda,
              const float* __restrict__ B, int ldb,
              float* __restrict__ C, int ldc,
              int N, int K,
              const float* __restrict__ bias) {
    __shared__ float As[8][128];
    __shared__ float Bs[8][128];
    const int tid = threadIdx.x;
    const int rowBase = blockIdx.y * 128;
    const int colBase = blockIdx.x * 128;
    const int kOff = (EPI == 3) ? blockIdx.z * K : 0;
    if (EPI == 3) C += (size_t)blockIdx.z * PSTRIDE;

    const int aRow = tid >> 1;
    const int aCol = (tid & 1) << 2;
    const float* Aptr = A + (long)(rowBase + aRow) * lda + aCol + kOff;
    const bool bValid = (colBase + aRow) < N;
    const float* Bptr = B + (long)(colBase + aRow) * ldb + aCol + kOff;

    const int tr = (tid >> 4) << 3;
    const int tc = (tid & 15) << 3;

    float acc[8][8];
    #pragma unroll
    for (int i = 0; i < 8; i++)
        #pragma unroll
        for (int j = 0; j < 8; j++) acc[i][j] = 0.0f;

    for (int k0 = 0; k0 < K; k0 += 8) {
        float4 va = *(const float4*)(Aptr + k0);
        float4 vb = bValid ? *(const float4*)(Bptr + k0) : make_float4(0.f, 0.f, 0.f, 0.f);
        As[aCol + 0][aRow] = va.x; As[aCol + 1][aRow] = va.y;
        As[aCol + 2][aRow] = va.z; As[aCol + 3][aRow] = va.w;
        Bs[aCol + 0][aRow] = vb.x; Bs[aCol + 1][aRow] = vb.y;
        Bs[aCol + 2][aRow] = vb.z; Bs[aCol + 3][aRow] = vb.w;
        __syncthreads();
        #pragma unroll
        for (int kk = 0; kk < 8; kk++) {
            float rm[8], rn[8];
            *(float4*)(rm)     = *(const float4*)&As[kk][tr];
            *(float4*)(rm + 4) = *(const float4*)&As[kk][tr + 4];
            *(float4*)(rn)     = *(const float4*)&Bs[kk][tc];
            *(float4*)(rn + 4) = *(const float4*)&Bs[kk][tc + 4];
            #pragma unroll
            for (int i = 0; i < 8; i++)
                #pragma unroll
                for (int j = 0; j < 8; j++)
                    acc[i][j] = fmaf(rm[i], rn[j], acc[i][j]);
        }
        __syncthreads();
    }

    #pragma unroll
    for (int i = 0; i < 8; i++) {
        const long rr = rowBase + tr + i;
        #pragma unroll
        for (int j = 0; j < 8; j++) {
            const int c = colBase + tc + j;
            if (c < N) {
                float v = acc[i][j];
                if (EPI == 1) v = softplusf(v + bias[c]);
                C[rr * ldc + c] = v;
            }
        }
    }
}

// ---------------- split-K reduction for x_proj ----------------
__global__ void splitk_reduce_kernel() {
    int i = blockIdx.x * blockDim.x + threadIdx.x;
    float s = 0.0f;
    #pragma unroll
    for (int p = 0; p < KSPL; p++) s += g_part[p * PSTRIDE + i];
    g_xdbl[i] = s;
}

// ---------------- host orchestration ----------------
extern "C" void kernel_launch(void* const* d_in, const int* in_sizes, int n_in,
                              void* d_out, int out_size) {
    const int*   ids        = (const int*)  d_in[0];
    const float* emb        = (const float*)d_in[1];
    const float* in_proj_w  = (const float*)d_in[2];
    const float* conv_w     = (const float*)d_in[3];
    const float* conv_b     = (const float*)d_in[4];
    const float* x_proj_w   = (const float*)d_in[5];
    const float* dt_proj_w  = (const float*)d_in[6];
    const float* dt_proj_b  = (const float*)d_in[7];
    const float* A_log      = (const float*)d_in[8];
    const float* D_param    = (const float*)d_in[9];
    const float* out_proj_w = (const float*)d_in[10];
    const float* norm_w     = (const float*)d_in[11];
    const float* norm_f_w   = (const float*)d_in[12];
    float* out = (float*)d_out;

    float *x, *xn, *xr, *xp, *xdbl, *delta, *y, *part;
    cudaGetSymbolAddress((void**)&x,     g_x);
    cudaGetSymbolAddress((void**)&xn,    g_xn);
    cudaGetSymbolAddress((void**)&xr,    g_xr);
    cudaGetSymbolAddress((void**)&xp,    g_xp);
    cudaGetSymbolAddress((void**)&xdbl,  g_xdbl);
    cudaGetSymbolAddress((void**)&delta, g_delta);
    cudaGetSymbolAddress((void**)&y,     g_y);
    cudaGetSymbolAddress((void**)&part,  g_part);

    embed_kernel<<<(LSEQ * DM) / 256, 256>>>(ids, emb);

    for (int layer = 0; layer < 2; layer++) {
        rmsnorm_kernel<<<LSEQ, 256>>>(x, norm_w + layer * DM, xn);

        // x_and_res = xn @ in_proj_w^T : [2048, 4096]   (tf32 mma, 128x256 tiles)
        mma_big<<<dim3((2 * DI) / 256, LSEQ / 128), 256>>>(
            xn, DM, in_proj_w + (size_t)layer * 2 * DI * DM, DM,
            xr, 2 * DI, 2 * DI, DM);

        conv_silu_kernel<<<(LSEQ * DI) / 256, 256>>>(
            conv_w + (size_t)layer * DI * 4, conv_b + (size_t)layer * DI);

        // x_dbl = xp @ x_proj_w^T : [2048, 96]  (fp32 split-K: 16 chunks of 128)
        sgemm_nt<3><<<dim3(1, LSEQ / 128, KSPL), 256>>>(
            xp, DI, x_proj_w + (size_t)layer * XDBL * DI, DI,
            part, XDBL, XDBL, DI / KSPL, (const float*)0);
        splitk_reduce_kernel<<<(LSEQ * XDBL) / 256, 256>>>();

        // delta = softplus(x_dbl[:, :64] @ dt_proj_w^T + b) : [2048, 2048]  (fp32)
        sgemm_nt<1><<<dim3(DI / 128, LSEQ / 128), 256>>>(
            xdbl, XDBL, dt_proj_w + (size_t)layer * DI * DTR, DTR,
            delta, DI, DI, DTR, dt_proj_b + (size_t)layer * DI);

        // scan + fused gate
        scan_kernel<<<(DI * DS) / 256, 256>>>(
            A_log + (size_t)layer * DI * DS, D_param + (size_t)layer * DI);

        // x = x + ygated @ out_proj_w^T : [2048, 1024]   (tf32 mma, 128x128 tiles)
        mma_nt<2><<<dim3(DM / 128, LSEQ / 128), 256>>>(
            y, DI, out_proj_w + (size_t)layer * DM * DI, DI,
            x, DM, DM, DI, x);
    }

    rmsnorm_kernel<<<LSEQ, 256>>>(x, norm_f_w, xn);

    // logits = xf @ embedding^T : [2048, 50264]   (tf32 mma, 128x256 tiles)
    mma_big<<<dim3((VOC + 255) / 256, LSEQ / 128), 256>>>(
        xn, DM, emb, DM, out, VOC, VOC, DM);
}

// round 9
// speedup vs baseline: 1.3155x; 1.3155x over previous
#include <cuda_runtime.h>
#include <cuda_bf16.h>
#include <stdint.h>
#include <cstdint>
#include <math.h>

#define DM   1024      // d_model
#define VOC  50264
#define DS   16        // d_state
#define DI   2048      // d_inner
#define DTR  64        // dt_rank
#define LSEQ 2048
#define XDBL 96        // dt_rank + 2*d_state
#define KSPL 16        // split-K factor for x_proj
#define PSTRIDE (LSEQ * XDBL)

// ---------------- scratch (device globals; no allocation allowed) ----------------
__device__ float g_x[LSEQ * DM];        // residual stream
__device__ float g_xn[LSEQ * DM];       // rmsnorm output
__device__ float g_xr[LSEQ * 2 * DI];   // in_proj output (x | res)
__device__ float g_xp[LSEQ * DI];       // post conv+silu
__device__ float g_xdbl[LSEQ * XDBL];   // x_proj output (dt | B | C)
__device__ float g_delta[LSEQ * DI];    // softplus(dt_proj)
__device__ float g_y[LSEQ * DI];        // scan output (gated in-scan)
__device__ float g_part[KSPL * PSTRIDE];  // split-K partials for x_proj

__device__ __forceinline__ float siluf(float x) { return x / (1.0f + __expf(-x)); }
__device__ __forceinline__ float softplusf(float x) {
    return (x > 20.0f) ? x : log1pf(expf(x));
}
__device__ __forceinline__ unsigned f2tf32(float f) {
    unsigned r; asm("cvt.rna.tf32.f32 %0, %1;" : "=r"(r) : "f"(f)); return r;
}
__device__ __forceinline__ void mma_tf32(float c[4], const unsigned a[4], const unsigned b[2]) {
    asm volatile(
        "mma.sync.aligned.m16n8k8.row.col.f32.tf32.tf32.f32 "
        "{%0,%1,%2,%3}, {%4,%5,%6,%7}, {%8,%9}, {%0,%1,%2,%3};"
        : "+f"(c[0]), "+f"(c[1]), "+f"(c[2]), "+f"(c[3])
        : "r"(a[0]), "r"(a[1]), "r"(a[2]), "r"(a[3]), "r"(b[0]), "r"(b[1]));
}

// ---------------- embedding gather ----------------
__global__ void embed_kernel(const int* __restrict__ ids, const float* __restrict__ emb) {
    int i = blockIdx.x * blockDim.x + threadIdx.x;
    int l = i >> 10, c = i & (DM - 1);
    g_x[i] = emb[(long)ids[l] * DM + c];
}

// ---------------- rmsnorm: one block per row ----------------
__global__ void rmsnorm_kernel(const float* __restrict__ x, const float* __restrict__ w,
                               float* __restrict__ out) {
    int row = blockIdx.x;
    const float* xr = x + row * DM;
    float s = 0.0f;
    for (int c = threadIdx.x; c < DM; c += blockDim.x) { float v = xr[c]; s += v * v; }
    __shared__ float red[32];
    #pragma unroll
    for (int o = 16; o; o >>= 1) s += __shfl_xor_sync(~0u, s, o);
    if ((threadIdx.x & 31) == 0) red[threadIdx.x >> 5] = s;
    __syncthreads();
    if (threadIdx.x < 32) {
        float v = (threadIdx.x < (blockDim.x >> 5)) ? red[threadIdx.x] : 0.0f;
        #pragma unroll
        for (int o = 16; o; o >>= 1) v += __shfl_xor_sync(~0u, v, o);
        if (threadIdx.x == 0) red[0] = v;
    }
    __syncthreads();
    float inv = rsqrtf(red[0] / (float)DM + 1e-5f);
    for (int c = threadIdx.x; c < DM; c += blockDim.x)
        out[row * DM + c] = xr[c] * inv * w[c];
}

// ---------------- causal depthwise conv1d (k=4) + bias + silu ----------------
__global__ void conv_silu_kernel(const float* __restrict__ cw, const float* __restrict__ cb) {
    int i = blockIdx.x * blockDim.x + threadIdx.x;
    int l = i >> 11, d = i & (DI - 1);
    float acc = cb[d];
    #pragma unroll
    for (int t = 0; t < 4; t++) {
        int ls = l - 3 + t;
        if (ls >= 0) acc = fmaf(cw[d * 4 + t], g_xr[ls * (2 * DI) + d], acc);
    }
    g_xp[i] = siluf(acc);
}

// ---------------- selective scan (gate fused): one thread per (d, n) ----------------
__global__ void scan_kernel(const float* __restrict__ A_log, const float* __restrict__ Dp) {
    int t = blockIdx.x * blockDim.x + threadIdx.x;
    int d = t >> 4, n = t & 15;
    float A_dn = -expf(A_log[d * DS + n]);
    float Dv = Dp[d];
    float h = 0.0f;
    for (int l = 0; l < LSEQ; l++) {
        float dl = g_delta[l * DI + d];
        float u  = g_xp[l * DI + d];
        float Bv = g_xdbl[l * XDBL + DTR + n];
        float Cv = g_xdbl[l * XDBL + DTR + DS + n];
        float dA = __expf(dl * A_dn);
        h = fmaf(dA, h, dl * u * Bv);
        float py = h * Cv;
        #pragma unroll
        for (int o = 8; o; o >>= 1) py += __shfl_xor_sync(~0u, py, o);
        if (n == 0) {
            float res = g_xr[l * (2 * DI) + DI + d];
            g_y[l * DI + d] = (py + u * Dv) * siluf(res);
        }
    }
}

// ================= TF32 mma.sync NT GEMM, 128x128 (proven) =================
// EPI: 0 = none, 1 = +bias then softplus, 2 = +residual.
template <int EPI>
__global__ __launch_bounds__(256, 2)
void mma_nt(const float* __restrict__ A, int lda,
            const float* __restrict__ B, int ldb,
            float* __restrict__ C, int ldc,
            int N, int K, const float* __restrict__ resid,
            const float* __restrict__ bias) {
    __shared__ unsigned sA[2][2][8][32][4];
    __shared__ unsigned sB[2][2][16][32][2];

    const int tid  = threadIdx.x;
    const int lane = tid & 31;
    const int warp = tid >> 5;
    const int wm = warp & 1;
    const int wn = warp >> 1;
    const int rowBase = blockIdx.y * 128;
    const int colBase = blockIdx.x * 128;

    const int r0  = tid >> 2;
    const int kq  = tid & 3;
    const float* Arow0 = A + (long)(rowBase + r0) * lda + kq * 4;
    const float* Arow1 = A + (long)(rowBase + r0 + 64) * lda + kq * 4;
    const int nIdx0 = colBase + r0;
    const int nIdx1 = colBase + r0 + 64;
    const float* Brow0 = B + (long)nIdx0 * ldb + kq * 4;
    const float* Brow1 = B + (long)nIdx1 * ldb + kq * 4;
    const bool bv0 = nIdx0 < N;
    const bool bv1 = nIdx1 < N;

    float acc[4][4][4];
    #pragma unroll
    for (int i = 0; i < 4; i++)
        #pragma unroll
        for (int j = 0; j < 4; j++)
            #pragma unroll
            for (int q = 0; q < 4; q++) acc[i][j][q] = 0.0f;

    float4 ra[2], rb[2];
    auto ldg = [&](int k0) {
        ra[0] = *(const float4*)(Arow0 + k0);
        ra[1] = *(const float4*)(Arow1 + k0);
        rb[0] = bv0 ? *(const float4*)(Brow0 + k0) : make_float4(0.f,0.f,0.f,0.f);
        rb[1] = bv1 ? *(const float4*)(Brow1 + k0) : make_float4(0.f,0.f,0.f,0.f);
    };
    auto sts = [&](int st) {
        const int k8 = kq >> 1;
        #pragma unroll
        for (int h = 0; h < 2; h++) {
            int row = r0 + h * 64;
            unsigned* pa = &sA[st][k8][row >> 4][(row & 7) * 4][(kq & 1) * 2 + ((row >> 3) & 1)];
            pa[0]  = f2tf32(ra[h].x);
            pa[4]  = f2tf32(ra[h].y);
            pa[8]  = f2tf32(ra[h].z);
            pa[12] = f2tf32(ra[h].w);
            unsigned* pb = &sB[st][k8][row >> 3][(row & 7) * 4][kq & 1];
            pb[0] = f2tf32(rb[h].x);
            pb[2] = f2tf32(rb[h].y);
            pb[4] = f2tf32(rb[h].z);
            pb[6] = f2tf32(rb[h].w);
        }
    };
    auto compute = [&](int st) {
        #pragma unroll
        for (int ks = 0; ks < 2; ks++) {
            unsigned af[4][4];
            unsigned bf[4][2];
            #pragma unroll
            for (int i = 0; i < 4; i++) {
                uint4 v = *(const uint4*)&sA[st][ks][wm * 4 + i][lane][0];
                af[i][0] = v.x; af[i][1] = v.y; af[i][2] = v.z; af[i][3] = v.w;
            }
            #pragma unroll
            for (int j = 0; j < 4; j++) {
                uint2 v = *(const uint2*)&sB[st][ks][wn * 4 + j][lane][0];
                bf[j][0] = v.x; bf[j][1] = v.y;
            }
            #pragma unroll
            for (int i = 0; i < 4; i++)
                #pragma unroll
                for (int j = 0; j < 4; j++)
                    mma_tf32(acc[i][j], af[i], bf[j]);
        }
    };

    ldg(0);
    sts(0);
    __syncthreads();
    int buf = 0;
    for (int k0 = 16; k0 < K; k0 += 16) {
        ldg(k0);
        compute(buf);
        sts(buf ^ 1);
        __syncthreads();
        buf ^= 1;
    }
    compute(buf);

    const int g   = lane >> 2;
    const int tig = lane & 3;
    #pragma unroll
    for (int i = 0; i < 4; i++) {
        const long row0 = rowBase + wm * 64 + i * 16 + g;
        #pragma unroll
        for (int j = 0; j < 4; j++) {
            const int col = colBase + wn * 32 + j * 8 + tig * 2;
            if (col < N) {
                float2 v01 = make_float2(acc[i][j][0], acc[i][j][1]);
                float2 v23 = make_float2(acc[i][j][2], acc[i][j][3]);
                if (EPI == 1) {
                    float b0 = bias[col], b1 = bias[col + 1];
                    v01.x = softplusf(v01.x + b0); v01.y = softplusf(v01.y + b1);
                    v23.x = softplusf(v23.x + b0); v23.y = softplusf(v23.y + b1);
                }
                if (EPI == 2) {
                    float2 t0 = *(const float2*)&resid[row0 * ldc + col];
                    float2 t1 = *(const float2*)&resid[(row0 + 8) * ldc + col];
                    v01.x += t0.x; v01.y += t0.y;
                    v23.x += t1.x; v23.y += t1.y;
                }
                *(float2*)&C[row0 * ldc + col]       = v01;
                *(float2*)&C[(row0 + 8) * ldc + col] = v23;
            }
        }
    }
}

// ---------------- fp32 NT SGEMM (split-K partials for x_proj) ----------------
__global__ __launch_bounds__(256, 2)
void sgemm_splitk(const float* __restrict__ A, int lda,
                  const float* __restrict__ B, int ldb,
                  float* __restrict__ C, int ldc,
                  int N, int K) {
    __shared__ float As[8][128];
    __shared__ float Bs[8][128];
    const int tid = threadIdx.x;
    const int rowBase = blockIdx.y * 128;
    const int colBase = blockIdx.x * 128;
    const int kOff = blockIdx.z * K;
    C += (size_t)blockIdx.z * PSTRIDE;

    const int aRow = tid >> 1;
    const int aCol = (tid & 1) << 2;
    const float* Aptr = A + (long)(rowBase + aRow) * lda + aCol + kOff;
    const bool bValid = (colBase + aRow) < N;
    const float* Bptr = B + (long)(colBase + aRow) * ldb + aCol + kOff;

    const int tr = (tid >> 4) << 3;
    const int tc = (tid & 15) << 3;

    float acc[8][8];
    #pragma unroll
    for (int i = 0; i < 8; i++)
        #pragma unroll
        for (int j = 0; j < 8; j++) acc[i][j] = 0.0f;

    for (int k0 = 0; k0 < K; k0 += 8) {
        float4 va = *(const float4*)(Aptr + k0);
        float4 vb = bValid ? *(const float4*)(Bptr + k0) : make_float4(0.f, 0.f, 0.f, 0.f);
        As[aCol + 0][aRow] = va.x; As[aCol + 1][aRow] = va.y;
        As[aCol + 2][aRow] = va.z; As[aCol + 3][aRow] = va.w;
        Bs[aCol + 0][aRow] = vb.x; Bs[aCol + 1][aRow] = vb.y;
        Bs[aCol + 2][aRow] = vb.z; Bs[aCol + 3][aRow] = vb.w;
        __syncthreads();
        #pragma unroll
        for (int kk = 0; kk < 8; kk++) {
            float rm[8], rn[8];
            *(float4*)(rm)     = *(const float4*)&As[kk][tr];
            *(float4*)(rm + 4) = *(const float4*)&As[kk][tr + 4];
            *(float4*)(rn)     = *(const float4*)&Bs[kk][tc];
            *(float4*)(rn + 4) = *(const float4*)&Bs[kk][tc + 4];
            #pragma unroll
            for (int i = 0; i < 8; i++)
                #pragma unroll
                for (int j = 0; j < 8; j++)
                    acc[i][j] = fmaf(rm[i], rn[j], acc[i][j]);
        }
        __syncthreads();
    }

    #pragma unroll
    for (int i = 0; i < 8; i++) {
        const long rr = rowBase + tr + i;
        #pragma unroll
        for (int j = 0; j < 8; j++) {
            const int c = colBase + tc + j;
            if (c < N) C[rr * ldc + c] = acc[i][j];
        }
    }
}

// ---------------- split-K reduction for x_proj ----------------
__global__ void splitk_reduce_kernel() {
    int i = blockIdx.x * blockDim.x + threadIdx.x;
    float s = 0.0f;
    #pragma unroll
    for (int p = 0; p < KSPL; p++) s += g_part[p * PSTRIDE + i];
    g_xdbl[i] = s;
}

// ---------------- host orchestration ----------------
extern "C" void kernel_launch(void* const* d_in, const int* in_sizes, int n_in,
                              void* d_out, int out_size) {
    const int*   ids        = (const int*)  d_in[0];
    const float* emb        = (const float*)d_in[1];
    const float* in_proj_w  = (const float*)d_in[2];
    const float* conv_w     = (const float*)d_in[3];
    const float* conv_b     = (const float*)d_in[4];
    const float* x_proj_w   = (const float*)d_in[5];
    const float* dt_proj_w  = (const float*)d_in[6];
    const float* dt_proj_b  = (const float*)d_in[7];
    const float* A_log      = (const float*)d_in[8];
    const float* D_param    = (const float*)d_in[9];
    const float* out_proj_w = (const float*)d_in[10];
    const float* norm_w     = (const float*)d_in[11];
    const float* norm_f_w   = (const float*)d_in[12];
    float* out = (float*)d_out;

    float *x, *xn, *xr, *xp, *xdbl, *delta, *y, *part;
    cudaGetSymbolAddress((void**)&x,     g_x);
    cudaGetSymbolAddress((void**)&xn,    g_xn);
    cudaGetSymbolAddress((void**)&xr,    g_xr);
    cudaGetSymbolAddress((void**)&xp,    g_xp);
    cudaGetSymbolAddress((void**)&xdbl,  g_xdbl);
    cudaGetSymbolAddress((void**)&delta, g_delta);
    cudaGetSymbolAddress((void**)&y,     g_y);
    cudaGetSymbolAddress((void**)&part,  g_part);

    embed_kernel<<<(LSEQ * DM) / 256, 256>>>(ids, emb);

    for (int layer = 0; layer < 2; layer++) {
        rmsnorm_kernel<<<LSEQ, 256>>>(x, norm_w + layer * DM, xn);

        // x_and_res = xn @ in_proj_w^T : [2048, 4096]   (tf32 mma 128x128)
        mma_nt<0><<<dim3((2 * DI) / 128, LSEQ / 128), 256>>>(
            xn, DM, in_proj_w + (size_t)layer * 2 * DI * DM, DM,
            xr, 2 * DI, 2 * DI, DM, (const float*)0, (const float*)0);

        conv_silu_kernel<<<(LSEQ * DI) / 256, 256>>>(
            conv_w + (size_t)layer * DI * 4, conv_b + (size_t)layer * DI);

        // x_dbl = xp @ x_proj_w^T : [2048, 96]  (fp32 split-K: 16 chunks of 128)
        sgemm_splitk<<<dim3(1, LSEQ / 128, KSPL), 256>>>(
            xp, DI, x_proj_w + (size_t)layer * XDBL * DI, DI,
            part, XDBL, XDBL, DI / KSPL);
        splitk_reduce_kernel<<<(LSEQ * XDBL) / 256, 256>>>();

        // delta = softplus(x_dbl[:, :64] @ dt_proj_w^T + b) : [2048, 2048]  (tf32 mma, K=64)
        mma_nt<1><<<dim3(DI / 128, LSEQ / 128), 256>>>(
            xdbl, XDBL, dt_proj_w + (size_t)layer * DI * DTR, DTR,
            delta, DI, DI, DTR, (const float*)0, dt_proj_b + (size_t)layer * DI);

        // scan + fused gate
        scan_kernel<<<(DI * DS) / 256, 256>>>(
            A_log + (size_t)layer * DI * DS, D_param + (size_t)layer * DI);

        // x = x + ygated @ out_proj_w^T : [2048, 1024]   (tf32 mma 128x128)
        mma_nt<2><<<dim3(DM / 128, LSEQ / 128), 256>>>(
            y, DI, out_proj_w + (size_t)layer * DM * DI, DI,
            x, DM, DM, DI, x, (const float*)0);
    }

    rmsnorm_kernel<<<LSEQ, 256>>>(x, norm_f_w, xn);

    // logits = xf @ embedding^T : [2048, 50264]   (tf32 mma 128x128)
    mma_nt<0><<<dim3((VOC + 127) / 128, LSEQ / 128), 256>>>(
        xn, DM, emb, DM, out, VOC, VOC, DM, (const float*)0, (const float*)0);
}

// round 10
// speedup vs baseline: 1.7740x; 1.3485x over previous
#include <cuda_runtime.h>
#include <cuda_bf16.h>
#include <stdint.h>
#include <cstdint>
#include <math.h>

#define DM   1024      // d_model
#define VOC  50264
#define DS   16        // d_state
#define DI   2048      // d_inner
#define DTR  64        // dt_rank
#define LSEQ 2048
#define XDBL 96        // dt_rank + 2*d_state
#define KSPL 16        // split-K factor for x_proj
#define PSTRIDE (LSEQ * XDBL)

// ---------------- scratch (device globals; no allocation allowed) ----------------
__device__ float g_x[LSEQ * DM];        // residual stream
__device__ float g_xn[LSEQ * DM];       // rmsnorm output
__device__ float g_xr[LSEQ * 2 * DI];   // in_proj output (x | res)
__device__ float g_xp[LSEQ * DI];       // post conv+silu
__device__ float g_xdbl[LSEQ * XDBL];   // x_proj output (dt | B | C)
__device__ float g_delta[LSEQ * DI];    // softplus(dt_proj)
__device__ float g_y[LSEQ * DI];        // scan output (gated in-scan)
__device__ float g_part[KSPL * PSTRIDE];  // split-K partials for x_proj

__device__ __forceinline__ float siluf(float x) { return x / (1.0f + __expf(-x)); }
__device__ __forceinline__ float softplusf(float x) {
    return (x > 20.0f) ? x : log1pf(expf(x));
}
__device__ __forceinline__ unsigned f2tf32(float f) {
    unsigned r; asm("cvt.rna.tf32.f32 %0, %1;" : "=r"(r) : "f"(f)); return r;
}
__device__ __forceinline__ void mma_tf32(float c[4], const unsigned a[4], const unsigned b[2]) {
    asm volatile(
        "mma.sync.aligned.m16n8k8.row.col.f32.tf32.tf32.f32 "
        "{%0,%1,%2,%3}, {%4,%5,%6,%7}, {%8,%9}, {%0,%1,%2,%3};"
        : "+f"(c[0]), "+f"(c[1]), "+f"(c[2]), "+f"(c[3])
        : "r"(a[0]), "r"(a[1]), "r"(a[2]), "r"(a[3]), "r"(b[0]), "r"(b[1]));
}

// ---------------- embedding gather ----------------
__global__ void embed_kernel(const int* __restrict__ ids, const float* __restrict__ emb) {
    int i = blockIdx.x * blockDim.x + threadIdx.x;
    int l = i >> 10, c = i & (DM - 1);
    g_x[i] = emb[(long)ids[l] * DM + c];
}

// ---------------- rmsnorm: one block per row ----------------
__global__ void rmsnorm_kernel(const float* __restrict__ x, const float* __restrict__ w,
                               float* __restrict__ out) {
    int row = blockIdx.x;
    const float* xr = x + row * DM;
    float s = 0.0f;
    for (int c = threadIdx.x; c < DM; c += blockDim.x) { float v = xr[c]; s += v * v; }
    __shared__ float red[32];
    #pragma unroll
    for (int o = 16; o; o >>= 1) s += __shfl_xor_sync(~0u, s, o);
    if ((threadIdx.x & 31) == 0) red[threadIdx.x >> 5] = s;
    __syncthreads();
    if (threadIdx.x < 32) {
        float v = (threadIdx.x < (blockDim.x >> 5)) ? red[threadIdx.x] : 0.0f;
        #pragma unroll
        for (int o = 16; o; o >>= 1) v += __shfl_xor_sync(~0u, v, o);
        if (threadIdx.x == 0) red[0] = v;
    }
    __syncthreads();
    float inv = rsqrtf(red[0] / (float)DM + 1e-5f);
    for (int c = threadIdx.x; c < DM; c += blockDim.x)
        out[row * DM + c] = xr[c] * inv * w[c];
}

// ---------------- causal depthwise conv1d (k=4) + bias + silu ----------------
__global__ void conv_silu_kernel(const float* __restrict__ cw, const float* __restrict__ cb) {
    int i = blockIdx.x * blockDim.x + threadIdx.x;
    int l = i >> 11, d = i & (DI - 1);
    float acc = cb[d];
    #pragma unroll
    for (int t = 0; t < 4; t++) {
        int ls = l - 3 + t;
        if (ls >= 0) acc = fmaf(cw[d * 4 + t], g_xr[ls * (2 * DI) + d], acc);
    }
    g_xp[i] = siluf(acc);
}

// ---------------- selective scan (gate fused, software-pipelined loads) ----------------
// one thread per (d, n); res/dl/u/Bv/Cv for iteration l+1 prefetched during compute of l.
__global__ void scan_kernel(const float* __restrict__ A_log, const float* __restrict__ Dp) {
    int t = blockIdx.x * blockDim.x + threadIdx.x;
    int d = t >> 4, n = t & 15;
    float A_dn = -expf(A_log[d * DS + n]);
    float Dv = Dp[d];
    float h = 0.0f;

    // preload iteration 0
    float dl  = g_delta[d];
    float u   = g_xp[d];
    float Bv  = g_xdbl[DTR + n];
    float Cv  = g_xdbl[DTR + DS + n];
    float res = g_xr[DI + d];

    for (int l = 0; l < LSEQ; l++) {
        // prefetch iteration l+1 (issued before the dependent compute chain)
        float dl2 = 0.f, u2 = 0.f, Bv2 = 0.f, Cv2 = 0.f, res2 = 0.f;
        if (l + 1 < LSEQ) {
            int l1 = l + 1;
            dl2  = g_delta[l1 * DI + d];
            u2   = g_xp[l1 * DI + d];
            Bv2  = g_xdbl[l1 * XDBL + DTR + n];
            Cv2  = g_xdbl[l1 * XDBL + DTR + DS + n];
            res2 = g_xr[l1 * (2 * DI) + DI + d];
        }

        float dA = __expf(dl * A_dn);
        h = fmaf(dA, h, dl * u * Bv);
        float py = h * Cv;
        #pragma unroll
        for (int o = 8; o; o >>= 1) py += __shfl_xor_sync(~0u, py, o);
        if (n == 0)
            g_y[l * DI + d] = (py + u * Dv) * siluf(res);

        dl = dl2; u = u2; Bv = Bv2; Cv = Cv2; res = res2;
    }
}

// ================= TF32 mma.sync NT GEMM, 128x128 (proven) =================
// EPI: 0 = none, 1 = +bias then softplus, 2 = +residual.
template <int EPI>
__global__ __launch_bounds__(256, 2)
void mma_nt(const float* __restrict__ A, int lda,
            const float* __restrict__ B, int ldb,
            float* __restrict__ C, int ldc,
            int N, int K, const float* __restrict__ resid,
            const float* __restrict__ bias) {
    __shared__ unsigned sA[2][2][8][32][4];
    __shared__ unsigned sB[2][2][16][32][2];

    const int tid  = threadIdx.x;
    const int lane = tid & 31;
    const int warp = tid >> 5;
    const int wm = warp & 1;
    const int wn = warp >> 1;
    const int rowBase = blockIdx.y * 128;
    const int colBase = blockIdx.x * 128;

    const int r0  = tid >> 2;
    const int kq  = tid & 3;
    const float* Arow0 = A + (long)(rowBase + r0) * lda + kq * 4;
    const float* Arow1 = A + (long)(rowBase + r0 + 64) * lda + kq * 4;
    const int nIdx0 = colBase + r0;
    const int nIdx1 = colBase + r0 + 64;
    const float* Brow0 = B + (long)nIdx0 * ldb + kq * 4;
    const float* Brow1 = B + (long)nIdx1 * ldb + kq * 4;
    const bool bv0 = nIdx0 < N;
    const bool bv1 = nIdx1 < N;

    float acc[4][4][4];
    #pragma unroll
    for (int i = 0; i < 4; i++)
        #pragma unroll
        for (int j = 0; j < 4; j++)
            #pragma unroll
            for (int q = 0; q < 4; q++) acc[i][j][q] = 0.0f;

    float4 ra[2], rb[2];
    auto ldg = [&](int k0) {
        ra[0] = *(const float4*)(Arow0 + k0);
        ra[1] = *(const float4*)(Arow1 + k0);
        rb[0] = bv0 ? *(const float4*)(Brow0 + k0) : make_float4(0.f,0.f,0.f,0.f);
        rb[1] = bv1 ? *(const float4*)(Brow1 + k0) : make_float4(0.f,0.f,0.f,0.f);
    };
    auto sts = [&](int st) {
        const int k8 = kq >> 1;
        #pragma unroll
        for (int h = 0; h < 2; h++) {
            int row = r0 + h * 64;
            unsigned* pa = &sA[st][k8][row >> 4][(row & 7) * 4][(kq & 1) * 2 + ((row >> 3) & 1)];
            pa[0]  = f2tf32(ra[h].x);
            pa[4]  = f2tf32(ra[h].y);
            pa[8]  = f2tf32(ra[h].z);
            pa[12] = f2tf32(ra[h].w);
            unsigned* pb = &sB[st][k8][row >> 3][(row & 7) * 4][kq & 1];
            pb[0] = f2tf32(rb[h].x);
            pb[2] = f2tf32(rb[h].y);
            pb[4] = f2tf32(rb[h].z);
            pb[6] = f2tf32(rb[h].w);
        }
    };
    auto compute = [&](int st) {
        #pragma unroll
        for (int ks = 0; ks < 2; ks++) {
            unsigned af[4][4];
            unsigned bf[4][2];
            #pragma unroll
            for (int i = 0; i < 4; i++) {
                uint4 v = *(const uint4*)&sA[st][ks][wm * 4 + i][lane][0];
                af[i][0] = v.x; af[i][1] = v.y; af[i][2] = v.z; af[i][3] = v.w;
            }
            #pragma unroll
            for (int j = 0; j < 4; j++) {
                uint2 v = *(const uint2*)&sB[st][ks][wn * 4 + j][lane][0];
                bf[j][0] = v.x; bf[j][1] = v.y;
            }
            #pragma unroll
            for (int i = 0; i < 4; i++)
                #pragma unroll
                for (int j = 0; j < 4; j++)
                    mma_tf32(acc[i][j], af[i], bf[j]);
        }
    };

    ldg(0);
    sts(0);
    __syncthreads();
    int buf = 0;
    for (int k0 = 16; k0 < K; k0 += 16) {
        ldg(k0);
        compute(buf);
        sts(buf ^ 1);
        __syncthreads();
        buf ^= 1;
    }
    compute(buf);

    const int g   = lane >> 2;
    const int tig = lane & 3;
    #pragma unroll
    for (int i = 0; i < 4; i++) {
        const long row0 = rowBase + wm * 64 + i * 16 + g;
        #pragma unroll
        for (int j = 0; j < 4; j++) {
            const int col = colBase + wn * 32 + j * 8 + tig * 2;
            if (col < N) {
                float2 v01 = make_float2(acc[i][j][0], acc[i][j][1]);
                float2 v23 = make_float2(acc[i][j][2], acc[i][j][3]);
                if (EPI == 1) {
                    float b0 = bias[col], b1 = bias[col + 1];
                    v01.x = softplusf(v01.x + b0); v01.y = softplusf(v01.y + b1);
                    v23.x = softplusf(v23.x + b0); v23.y = softplusf(v23.y + b1);
                }
                if (EPI == 2) {
                    float2 t0 = *(const float2*)&resid[row0 * ldc + col];
                    float2 t1 = *(const float2*)&resid[(row0 + 8) * ldc + col];
                    v01.x += t0.x; v01.y += t0.y;
                    v23.x += t1.x; v23.y += t1.y;
                }
                *(float2*)&C[row0 * ldc + col]       = v01;
                *(float2*)&C[(row0 + 8) * ldc + col] = v23;
            }
        }
    }
}

// ---------------- fp32 NT SGEMM (split-K partials for x_proj) ----------------
__global__ __launch_bounds__(256, 2)
void sgemm_splitk(const float* __restrict__ A, int lda,
                  const float* __restrict__ B, int ldb,
                  float* __restrict__ C, int ldc,
                  int N, int K) {
    __shared__ float As[8][128];
    __shared__ float Bs[8][128];
    const int tid = threadIdx.x;
    const int rowBase = blockIdx.y * 128;
    const int colBase = blockIdx.x * 128;
    const int kOff = blockIdx.z * K;
    C += (size_t)blockIdx.z * PSTRIDE;

    const int aRow = tid >> 1;
    const int aCol = (tid & 1) << 2;
    const float* Aptr = A + (long)(rowBase + aRow) * lda + aCol + kOff;
    const bool bValid = (colBase + aRow) < N;
    const float* Bptr = B + (long)(colBase + aRow) * ldb + aCol + kOff;

    const int tr = (tid >> 4) << 3;
    const int tc = (tid & 15) << 3;

    float acc[8][8];
    #pragma unroll
    for (int i = 0; i < 8; i++)
        #pragma unroll
        for (int j = 0; j < 8; j++) acc[i][j] = 0.0f;

    for (int k0 = 0; k0 < K; k0 += 8) {
        float4 va = *(const float4*)(Aptr + k0);
        float4 vb = bValid ? *(const float4*)(Bptr + k0) : make_float4(0.f, 0.f, 0.f, 0.f);
        As[aCol + 0][aRow] = va.x; As[aCol + 1][aRow] = va.y;
        As[aCol + 2][aRow] = va.z; As[aCol + 3][aRow] = va.w;
        Bs[aCol + 0][aRow] = vb.x; Bs[aCol + 1][aRow] = vb.y;
        Bs[aCol + 2][aRow] = vb.z; Bs[aCol + 3][aRow] = vb.w;
        __syncthreads();
        #pragma unroll
        for (int kk = 0; kk < 8; kk++) {
            float rm[8], rn[8];
            *(float4*)(rm)     = *(const float4*)&As[kk][tr];
            *(float4*)(rm + 4) = *(const float4*)&As[kk][tr + 4];
            *(float4*)(rn)     = *(const float4*)&Bs[kk][tc];
            *(float4*)(rn + 4) = *(const float4*)&Bs[kk][tc + 4];
            #pragma unroll
            for (int i = 0; i < 8; i++)
                #pragma unroll
                for (int j = 0; j < 8; j++)
                    acc[i][j] = fmaf(rm[i], rn[j], acc[i][j]);
        }
        __syncthreads();
    }

    #pragma unroll
    for (int i = 0; i < 8; i++) {
        const long rr = rowBase + tr + i;
        #pragma unroll
        for (int j = 0; j < 8; j++) {
            const int c = colBase + tc + j;
            if (c < N) C[rr * ldc + c] = acc[i][j];
        }
    }
}

// ---------------- split-K reduction for x_proj ----------------
__global__ void splitk_reduce_kernel() {
    int i = blockIdx.x * blockDim.x + threadIdx.x;
    float s = 0.0f;
    #pragma unroll
    for (int p = 0; p < KSPL; p++) s += g_part[p * PSTRIDE + i];
    g_xdbl[i] = s;
}

// ---------------- host orchestration ----------------
extern "C" void kernel_launch(void* const* d_in, const int* in_sizes, int n_in,
                              void* d_out, int out_size) {
    const int*   ids        = (const int*)  d_in[0];
    const float* emb        = (const float*)d_in[1];
    const float* in_proj_w  = (const float*)d_in[2];
    const float* conv_w     = (const float*)d_in[3];
    const float* conv_b     = (const float*)d_in[4];
    const float* x_proj_w   = (const float*)d_in[5];
    const float* dt_proj_w  = (const float*)d_in[6];
    const float* dt_proj_b  = (const float*)d_in[7];
    const float* A_log      = (const float*)d_in[8];
    const float* D_param    = (const float*)d_in[9];
    const float* out_proj_w = (const float*)d_in[10];
    const float* norm_w     = (const float*)d_in[11];
    const float* norm_f_w   = (const float*)d_in[12];
    float* out = (float*)d_out;

    float *x, *xn, *xr, *xp, *xdbl, *delta, *y, *part;
    cudaGetSymbolAddress((void**)&x,     g_x);
    cudaGetSymbolAddress((void**)&xn,    g_xn);
    cudaGetSymbolAddress((void**)&xr,    g_xr);
    cudaGetSymbolAddress((void**)&xp,    g_xp);
    cudaGetSymbolAddress((void**)&xdbl,  g_xdbl);
    cudaGetSymbolAddress((void**)&delta, g_delta);
    cudaGetSymbolAddress((void**)&y,     g_y);
    cudaGetSymbolAddress((void**)&part,  g_part);

    embed_kernel<<<(LSEQ * DM) / 256, 256>>>(ids, emb);

    for (int layer = 0; layer < 2; layer++) {
        rmsnorm_kernel<<<LSEQ, 256>>>(x, norm_w + layer * DM, xn);

        // x_and_res = xn @ in_proj_w^T : [2048, 4096]   (tf32 mma 128x128)
        mma_nt<0><<<dim3((2 * DI) / 128, LSEQ / 128), 256>>>(
            xn, DM, in_proj_w + (size_t)layer * 2 * DI * DM, DM,
            xr, 2 * DI, 2 * DI, DM, (const float*)0, (const float*)0);

        conv_silu_kernel<<<(LSEQ * DI) / 256, 256>>>(
            conv_w + (size_t)layer * DI * 4, conv_b + (size_t)layer * DI);

        // x_dbl = xp @ x_proj_w^T : [2048, 96]  (fp32 split-K: 16 chunks of 128)
        sgemm_splitk<<<dim3(1, LSEQ / 128, KSPL), 256>>>(
            xp, DI, x_proj_w + (size_t)layer * XDBL * DI, DI,
            part, XDBL, XDBL, DI / KSPL);
        splitk_reduce_kernel<<<(LSEQ * XDBL) / 256, 256>>>();

        // delta = softplus(x_dbl[:, :64] @ dt_proj_w^T + b) : [2048, 2048]  (tf32 mma, K=64)
        mma_nt<1><<<dim3(DI / 128, LSEQ / 128), 256>>>(
            xdbl, XDBL, dt_proj_w + (size_t)layer * DI * DTR, DTR,
            delta, DI, DI, DTR, (const float*)0, dt_proj_b + (size_t)layer * DI);

        // scan + fused gate (pipelined loads)
        scan_kernel<<<(DI * DS) / 256, 256>>>(
            A_log + (size_t)layer * DI * DS, D_param + (size_t)layer * DI);

        // x = x + ygated @ out_proj_w^T : [2048, 1024]   (tf32 mma 128x128)
        mma_nt<2><<<dim3(DM / 128, LSEQ / 128), 256>>>(
            y, DI, out_proj_w + (size_t)layer * DM * DI, DI,
            x, DM, DM, DI, x, (const float*)0);
    }

    rmsnorm_kernel<<<LSEQ, 256>>>(x, norm_f_w, xn);

    // logits = xf @ embedding^T : [2048, 50264]   (tf32 mma 128x128)
    mma_nt<0><<<dim3((VOC + 127) / 128, LSEQ / 128), 256>>>(
        xn, DM, emb, DM, out, VOC, VOC, DM, (const float*)0, (const float*)0);
}

// round 12
// speedup vs baseline: 2.7473x; 1.5487x over previous
#include <cuda_runtime.h>
#include <cuda_bf16.h>
#include <cuda_fp16.h>
#include <stdint.h>
#include <cstdint>
#include <math.h>

#define DM   1024      // d_model
#define VOC  50264
#define DS   16        // d_state
#define DI   2048      // d_inner
#define DTR  64        // dt_rank
#define LSEQ 2048
#define XDBL 96        // dt_rank + 2*d_state
#define KSPL 16        // split-K factor for x_proj
#define PSTRIDE (LSEQ * XDBL)

// ---------------- scratch (device globals; no allocation allowed) ----------------
__device__ float g_x[LSEQ * DM];        // residual stream
__device__ float g_xn[LSEQ * DM];       // rmsnorm output
__device__ float g_xr[LSEQ * 2 * DI];   // in_proj output (x | res)
__device__ float g_xp[LSEQ * DI];       // post conv+silu
__device__ float g_xdbl[LSEQ * XDBL];   // x_proj output (dt | B | C)
__device__ float g_delta[LSEQ * DI];    // softplus(dt_proj)
__device__ float g_y[LSEQ * DI];        // scan output / gated
__device__ float g_part[KSPL * PSTRIDE];  // split-K partials for x_proj

__device__ __forceinline__ float siluf(float x) { return x / (1.0f + __expf(-x)); }
__device__ __forceinline__ float softplusf(float x) {
    return (x > 20.0f) ? x : log1pf(expf(x));
}
// pack two fp32 into half2 bits (rn rounding; same 11-bit significand as tf32)
__device__ __forceinline__ unsigned pkh2(float x, float y) {
    __half2 h = __floats2half2_rn(x, y);
    return *(unsigned*)&h;
}
__device__ __forceinline__ void mma_f16(float c[4], const unsigned a[4], const unsigned b[2]) {
    asm volatile(
        "mma.sync.aligned.m16n8k16.row.col.f32.f16.f16.f32 "
        "{%0,%1,%2,%3}, {%4,%5,%6,%7}, {%8,%9}, {%0,%1,%2,%3};"
        : "+f"(c[0]), "+f"(c[1]), "+f"(c[2]), "+f"(c[3])
        : "r"(a[0]), "r"(a[1]), "r"(a[2]), "r"(a[3]), "r"(b[0]), "r"(b[1]));
}

// ---------------- embedding gather ----------------
__global__ void embed_kernel(const int* __restrict__ ids, const float* __restrict__ emb) {
    int i = blockIdx.x * blockDim.x + threadIdx.x;
    int l = i >> 10, c = i & (DM - 1);
    g_x[i] = emb[(long)ids[l] * DM + c];
}

// ---------------- rmsnorm: one block per row ----------------
__global__ void rmsnorm_kernel(const float* __restrict__ x, const float* __restrict__ w,
                               float* __restrict__ out) {
    int row = blockIdx.x;
    const float* xr = x + row * DM;
    float s = 0.0f;
    for (int c = threadIdx.x; c < DM; c += blockDim.x) { float v = xr[c]; s += v * v; }
    __shared__ float red[32];
    #pragma unroll
    for (int o = 16; o; o >>= 1) s += __shfl_xor_sync(~0u, s, o);
    if ((threadIdx.x & 31) == 0) red[threadIdx.x >> 5] = s;
    __syncthreads();
    if (threadIdx.x < 32) {
        float v = (threadIdx.x < (blockDim.x >> 5)) ? red[threadIdx.x] : 0.0f;
        #pragma unroll
        for (int o = 16; o; o >>= 1) v += __shfl_xor_sync(~0u, v, o);
        if (threadIdx.x == 0) red[0] = v;
    }
    __syncthreads();
    float inv = rsqrtf(red[0] / (float)DM + 1e-5f);
    for (int c = threadIdx.x; c < DM; c += blockDim.x)
        out[row * DM + c] = xr[c] * inv * w[c];
}

// ---------------- causal depthwise conv1d (k=4) + bias + silu ----------------
__global__ void conv_silu_kernel(const float* __restrict__ cw, const float* __restrict__ cb) {
    int i = blockIdx.x * blockDim.x + threadIdx.x;
    int l = i >> 11, d = i & (DI - 1);
    float acc = cb[d];
    #pragma unroll
    for (int t = 0; t < 4; t++) {
        int ls = l - 3 + t;
        if (ls >= 0) acc = fmaf(cw[d * 4 + t], g_xr[ls * (2 * DI) + d], acc);
    }
    g_xp[i] = siluf(acc);
}

// ---------------- selective scan: one thread per (d, n)  (round-4 proven form) ----------------
__global__ void scan_kernel(const float* __restrict__ A_log, const float* __restrict__ Dp) {
    int t = blockIdx.x * blockDim.x + threadIdx.x;
    int d = t >> 4, n = t & 15;
    float A_dn = -expf(A_log[d * DS + n]);
    float Dv = Dp[d];
    float h = 0.0f;
    for (int l = 0; l < LSEQ; l++) {
        float dl = g_delta[l * DI + d];
        float u  = g_xp[l * DI + d];
        float Bv = g_xdbl[l * XDBL + DTR + n];
        float Cv = g_xdbl[l * XDBL + DTR + DS + n];
        float dA = __expf(dl * A_dn);
        h = fmaf(dA, h, dl * u * Bv);
        float py = h * Cv;
        #pragma unroll
        for (int o = 8; o; o >>= 1) py += __shfl_xor_sync(~0u, py, o);
        if (n == 0) g_y[l * DI + d] = py + u * Dv;
    }
}

// ---------------- gate: y *= silu(res)  (separate, round-4 proven form) ----------------
__global__ void gate_kernel() {
    int i = blockIdx.x * blockDim.x + threadIdx.x;
    int l = i >> 11, d = i & (DI - 1);
    g_y[i] = g_y[i] * siluf(g_xr[l * (2 * DI) + DI + d]);
}

// ================= FP16 mma.sync m16n8k16 NT GEMM, 128x128, double-buffered =================
// C[M,N] = A[M,K]*B[N,K]^T, fp32 accumulate (fp16 significand == tf32 significand).
// EPI: 0 = none, 1 = +bias then softplus, 2 = +residual.
// Block 256 thr = 8 warps (2x4), warp tile 64x32, BK=16 (one k16 mma step).
template <int EPI>
__global__ __launch_bounds__(256, 2)
void mma_nt(const float* __restrict__ A, int lda,
            const float* __restrict__ B, int ldb,
            float* __restrict__ C, int ldc,
            int N, int K, const float* __restrict__ resid,
            const float* __restrict__ bias) {
    __shared__ unsigned sA[2][8][32][4];    // [stage][mtile16][lane][areg]  8 KB
    __shared__ unsigned sB[2][16][32][2];   // [stage][ntile8][lane][breg]   8 KB

    const int tid  = threadIdx.x;
    const int lane = tid & 31;
    const int warp = tid >> 5;
    const int wm = warp & 1;
    const int wn = warp >> 1;
    const int rowBase = blockIdx.y * 128;
    const int colBase = blockIdx.x * 128;

    // global load: thread handles rows r0, r0+64; float4 kq covers k = 4*kq..4*kq+3
    const int r0  = tid >> 2;
    const int kq  = tid & 3;
    const float* Arow0 = A + (long)(rowBase + r0) * lda + kq * 4;
    const float* Arow1 = A + (long)(rowBase + r0 + 64) * lda + kq * 4;
    const int nIdx0 = colBase + r0;
    const int nIdx1 = colBase + r0 + 64;
    const float* Brow0 = B + (long)nIdx0 * ldb + kq * 4;
    const float* Brow1 = B + (long)nIdx1 * ldb + kq * 4;
    const bool bv0 = nIdx0 < N;
    const bool bv1 = nIdx1 < N;

    float acc[4][4][4];
    #pragma unroll
    for (int i = 0; i < 4; i++)
        #pragma unroll
        for (int j = 0; j < 4; j++)
            #pragma unroll
            for (int q = 0; q < 4; q++) acc[i][j][q] = 0.0f;

    float4 ra[2], rb[2];
    auto ldg = [&](int k0) {
        ra[0] = *(const float4*)(Arow0 + k0);
        ra[1] = *(const float4*)(Arow1 + k0);
        rb[0] = bv0 ? *(const float4*)(Brow0 + k0) : make_float4(0.f,0.f,0.f,0.f);
        rb[1] = bv1 ? *(const float4*)(Brow1 + k0) : make_float4(0.f,0.f,0.f,0.f);
    };
    // scatter into m16n8k16 fragment layout:
    // A: reg = (rt>>3) + 2*(k>>3), lane = ((rt&7)<<2) | ((k>>1)&3), half = k&1
    // B: reg = k>>3,               lane = ((ct&7)<<2) | ((k>>1)&3)
    auto sts = [&](int st) {
        const int kcLo = (2 * kq) & 3;       // k = 4kq, 4kq+1
        const int kcHi = (2 * kq + 1) & 3;   // k = 4kq+2, 4kq+3
        const int kr   = kq >> 1;            // k>>3 for this float4
        #pragma unroll
        for (int h = 0; h < 2; h++) {
            const int row = r0 + h * 64;
            const float4 va = ra[h];
            const float4 vb = rb[h];
            // A
            const int mt = row >> 4, rt = row & 15;
            const int lr = (rt & 7) << 2;
            const int rA = (rt >> 3) + 2 * kr;
            sA[st][mt][lr | kcLo][rA] = pkh2(va.x, va.y);
            sA[st][mt][lr | kcHi][rA] = pkh2(va.z, va.w);
            // B
            const int nt = row >> 3, ct = row & 7;
            const int lb = ct << 2;
            sB[st][nt][lb | kcLo][kr] = pkh2(vb.x, vb.y);
            sB[st][nt][lb | kcHi][kr] = pkh2(vb.z, vb.w);
        }
    };
    auto compute = [&](int st) {
        unsigned af[4][4];
        unsigned bf[4][2];
        #pragma unroll
        for (int i = 0; i < 4; i++) {
            uint4 v = *(const uint4*)&sA[st][wm * 4 + i][lane][0];
            af[i][0] = v.x; af[i][1] = v.y; af[i][2] = v.z; af[i][3] = v.w;
        }
        #pragma unroll
        for (int j = 0; j < 4; j++) {
            uint2 v = *(const uint2*)&sB[st][wn * 4 + j][lane][0];
            bf[j][0] = v.x; bf[j][1] = v.y;
        }
        #pragma unroll
        for (int i = 0; i < 4; i++)
            #pragma unroll
            for (int j = 0; j < 4; j++)
                mma_f16(acc[i][j], af[i], bf[j]);
    };

    ldg(0);
    sts(0);
    __syncthreads();
    int buf = 0;
    for (int k0 = 16; k0 < K; k0 += 16) {
        ldg(k0);
        compute(buf);
        sts(buf ^ 1);
        __syncthreads();
        buf ^= 1;
    }
    compute(buf);

    const int g   = lane >> 2;
    const int tig = lane & 3;
    #pragma unroll
    for (int i = 0; i < 4; i++) {
        const long row0 = rowBase + wm * 64 + i * 16 + g;
        #pragma unroll
        for (int j = 0; j < 4; j++) {
            const int col = colBase + wn * 32 + j * 8 + tig * 2;
            if (col < N) {
                float2 v01 = make_float2(acc[i][j][0], acc[i][j][1]);
                float2 v23 = make_float2(acc[i][j][2], acc[i][j][3]);
                if (EPI == 1) {
                    float b0 = bias[col], b1 = bias[col + 1];
                    v01.x = softplusf(v01.x + b0); v01.y = softplusf(v01.y + b1);
                    v23.x = softplusf(v23.x + b0); v23.y = softplusf(v23.y + b1);
                }
                if (EPI == 2) {
                    float2 t0 = *(const float2*)&resid[row0 * ldc + col];
                    float2 t1 = *(const float2*)&resid[(row0 + 8) * ldc + col];
                    v01.x += t0.x; v01.y += t0.y;
                    v23.x += t1.x; v23.y += t1.y;
                }
                *(float2*)&C[row0 * ldc + col]       = v01;
                *(float2*)&C[(row0 + 8) * ldc + col] = v23;
            }
        }
    }
}

// ---------------- fp32 NT SGEMM (split-K partials for x_proj; exact path) ----------------
__global__ __launch_bounds__(256, 2)
void sgemm_splitk(const float* __restrict__ A, int lda,
                  const float* __restrict__ B, int ldb,
                  float* __restrict__ C, int ldc,
                  int N, int K) {
    __shared__ float As[8][128];
    __shared__ float Bs[8][128];
    const int tid = threadIdx.x;
    const int rowBase = blockIdx.y * 128;
    const int colBase = blockIdx.x * 128;
    const int kOff = blockIdx.z * K;
    C += (size_t)blockIdx.z * PSTRIDE;

    const int aRow = tid >> 1;
    const int aCol = (tid & 1) << 2;
    const float* Aptr = A + (long)(rowBase + aRow) * lda + aCol + kOff;
    const bool bValid = (colBase + aRow) < N;
    const float* Bptr = B + (long)(colBase + aRow) * ldb + aCol + kOff;

    const int tr = (tid >> 4) << 3;
    const int tc = (tid & 15) << 3;

    float acc[8][8];
    #pragma unroll
    for (int i = 0; i < 8; i++)
        #pragma unroll
        for (int j = 0; j < 8; j++) acc[i][j] = 0.0f;

    for (int k0 = 0; k0 < K; k0 += 8) {
        float4 va = *(const float4*)(Aptr + k0);
        float4 vb = bValid ? *(const float4*)(Bptr + k0) : make_float4(0.f, 0.f, 0.f, 0.f);
        As[aCol + 0][aRow] = va.x; As[aCol + 1][aRow] = va.y;
        As[aCol + 2][aRow] = va.z; As[aCol + 3][aRow] = va.w;
        Bs[aCol + 0][aRow] = vb.x; Bs[aCol + 1][aRow] = vb.y;
        Bs[aCol + 2][aRow] = vb.z; Bs[aCol + 3][aRow] = vb.w;
        __syncthreads();
        #pragma unroll
        for (int kk = 0; kk < 8; kk++) {
            float rm[8], rn[8];
            *(float4*)(rm)     = *(const float4*)&As[kk][tr];
            *(float4*)(rm + 4) = *(const float4*)&As[kk][tr + 4];
            *(float4*)(rn)     = *(const float4*)&Bs[kk][tc];
            *(float4*)(rn + 4) = *(const float4*)&Bs[kk][tc + 4];
            #pragma unroll
            for (int i = 0; i < 8; i++)
                #pragma unroll
                for (int j = 0; j < 8; j++)
                    acc[i][j] = fmaf(rm[i], rn[j], acc[i][j]);
        }
        __syncthreads();
    }

    #pragma unroll
    for (int i = 0; i < 8; i++) {
        const long rr = rowBase + tr + i;
        #pragma unroll
        for (int j = 0; j < 8; j++) {
            const int c = colBase + tc + j;
            if (c < N) C[rr * ldc + c] = acc[i][j];
        }
    }
}

// ---------------- split-K reduction for x_proj ----------------
__global__ void splitk_reduce_kernel() {
    int i = blockIdx.x * blockDim.x + threadIdx.x;
    float s = 0.0f;
    #pragma unroll
    for (int p = 0; p < KSPL; p++) s += g_part[p * PSTRIDE + i];
    g_xdbl[i] = s;
}

// ---------------- host orchestration ----------------
extern "C" void kernel_launch(void* const* d_in, const int* in_sizes, int n_in,
                              void* d_out, int out_size) {
    const int*   ids        = (const int*)  d_in[0];
    const float* emb        = (const float*)d_in[1];
    const float* in_proj_w  = (const float*)d_in[2];
    const float* conv_w     = (const float*)d_in[3];
    const float* conv_b     = (const float*)d_in[4];
    const float* x_proj_w   = (const float*)d_in[5];
    const float* dt_proj_w  = (const float*)d_in[6];
    const float* dt_proj_b  = (const float*)d_in[7];
    const float* A_log      = (const float*)d_in[8];
    const float* D_param    = (const float*)d_in[9];
    const float* out_proj_w = (const float*)d_in[10];
    const float* norm_w     = (const float*)d_in[11];
    const float* norm_f_w   = (const float*)d_in[12];
    float* out = (float*)d_out;

    float *x, *xn, *xr, *xp, *xdbl, *delta, *y, *part;
    cudaGetSymbolAddress((void**)&x,     g_x);
    cudaGetSymbolAddress((void**)&xn,    g_xn);
    cudaGetSymbolAddress((void**)&xr,    g_xr);
    cudaGetSymbolAddress((void**)&xp,    g_xp);
    cudaGetSymbolAddress((void**)&xdbl,  g_xdbl);
    cudaGetSymbolAddress((void**)&delta, g_delta);
    cudaGetSymbolAddress((void**)&y,     g_y);
    cudaGetSymbolAddress((void**)&part,  g_part);

    embed_kernel<<<(LSEQ * DM) / 256, 256>>>(ids, emb);

    for (int layer = 0; layer < 2; layer++) {
        rmsnorm_kernel<<<LSEQ, 256>>>(x, norm_w + layer * DM, xn);

        // x_and_res = xn @ in_proj_w^T : [2048, 4096]   (fp16 mma 128x128)
        mma_nt<0><<<dim3((2 * DI) / 128, LSEQ / 128), 256>>>(
            xn, DM, in_proj_w + (size_t)layer * 2 * DI * DM, DM,
            xr, 2 * DI, 2 * DI, DM, (const float*)0, (const float*)0);

        conv_silu_kernel<<<(LSEQ * DI) / 256, 256>>>(
            conv_w + (size_t)layer * DI * 4, conv_b + (size_t)layer * DI);

        // x_dbl = xp @ x_proj_w^T : [2048, 96]  (fp32 split-K: 16 chunks of 128)
        sgemm_splitk<<<dim3(1, LSEQ / 128, KSPL), 256>>>(
            xp, DI, x_proj_w + (size_t)layer * XDBL * DI, DI,
            part, XDBL, XDBL, DI / KSPL);
        splitk_reduce_kernel<<<(LSEQ * XDBL) / 256, 256>>>();

        // delta = softplus(x_dbl[:, :64] @ dt_proj_w^T + b) : [2048, 2048]  (fp16 mma, K=64)
        mma_nt<1><<<dim3(DI / 128, LSEQ / 128), 256>>>(
            xdbl, XDBL, dt_proj_w + (size_t)layer * DI * DTR, DTR,
            delta, DI, DI, DTR, (const float*)0, dt_proj_b + (size_t)layer * DI);

        // scan, then separate gate (proven round-4 structure)
        scan_kernel<<<(DI * DS) / 256, 256>>>(
            A_log + (size_t)layer * DI * DS, D_param + (size_t)layer * DI);
        gate_kernel<<<(LSEQ * DI) / 256, 256>>>();

        // x = x + ygated @ out_proj_w^T : [2048, 1024]   (fp16 mma 128x128)
        mma_nt<2><<<dim3(DM / 128, LSEQ / 128), 256>>>(
            y, DI, out_proj_w + (size_t)layer * DM * DI, DI,
            x, DM, DM, DI, x, (const float*)0);
    }

    rmsnorm_kernel<<<LSEQ, 256>>>(x, norm_f_w, xn);

    // logits = xf @ embedding^T : [2048, 50264]   (fp16 mma 128x128)
    mma_nt<0><<<dim3((VOC + 127) / 128, LSEQ / 128), 256>>>(
        xn, DM, emb, DM, out, VOC, VOC, DM, (const float*)0, (const float*)0);
}

// round 14
// speedup vs baseline: 4.3350x; 1.5779x over previous
#include <cuda_runtime.h>
#include <cuda_bf16.h>
#include <cuda_fp16.h>
#include <stdint.h>
#include <cstdint>
#include <math.h>

#define DM   1024      // d_model
#define VOC  50264
#define DS   16        // d_state
#define DI   2048      // d_inner
#define DTR  64        // dt_rank
#define LSEQ 2048
#define XDBL 96        // dt_rank + 2*d_state
#define KSPL 16        // split-K factor for x_proj
#define PSTRIDE (LSEQ * XDBL)
#define SCH  8         // scan chunks
#define CL   (LSEQ / SCH)
#define NDN  (DI * DS) // 32768

// ---------------- scratch (device globals; no allocation allowed) ----------------
__device__ float g_x[LSEQ * DM];        // residual stream
__device__ float g_xn[LSEQ * DM];       // rmsnorm output
__device__ float g_xr[LSEQ * 2 * DI];   // in_proj output (x | res)
__device__ float g_xp[LSEQ * DI];       // post conv+silu
__device__ float g_xdbl[LSEQ * XDBL];   // x_proj output (dt | B | C)
__device__ float g_delta[LSEQ * DI];    // softplus(dt_proj)
__device__ float g_y[LSEQ * DI];        // scan output / gated
__device__ float g_part[KSPL * PSTRIDE];  // split-K partials for x_proj
__device__ float g_cp[SCH * NDN];       // scan chunk carry: product of dA
__device__ float g_ce[SCH * NDN];       // scan chunk carry: zero-start end state
__device__ float g_h0[SCH * NDN];       // scan chunk true start state

__device__ __forceinline__ float siluf(float x) { return x / (1.0f + __expf(-x)); }
__device__ __forceinline__ float softplusf(float x) {
    return (x > 20.0f) ? x : log1pf(expf(x));
}
// pack two fp32 into half2 bits (rn rounding; same 11-bit significand as tf32)
__device__ __forceinline__ unsigned pkh2(float x, float y) {
    __half2 h = __floats2half2_rn(x, y);
    return *(unsigned*)&h;
}
__device__ __forceinline__ void mma_f16(float c[4], const unsigned a[4], const unsigned b[2]) {
    asm volatile(
        "mma.sync.aligned.m16n8k16.row.col.f32.f16.f16.f32 "
        "{%0,%1,%2,%3}, {%4,%5,%6,%7}, {%8,%9}, {%0,%1,%2,%3};"
        : "+f"(c[0]), "+f"(c[1]), "+f"(c[2]), "+f"(c[3])
        : "r"(a[0]), "r"(a[1]), "r"(a[2]), "r"(a[3]), "r"(b[0]), "r"(b[1]));
}

// ---------------- embedding gather ----------------
__global__ void embed_kernel(const int* __restrict__ ids, const float* __restrict__ emb) {
    int i = blockIdx.x * blockDim.x + threadIdx.x;
    int l = i >> 10, c = i & (DM - 1);
    g_x[i] = emb[(long)ids[l] * DM + c];
}

// ---------------- rmsnorm: one block per row ----------------
__global__ void rmsnorm_kernel(const float* __restrict__ x, const float* __restrict__ w,
                               float* __restrict__ out) {
    int row = blockIdx.x;
    const float* xr = x + row * DM;
    float s = 0.0f;
    for (int c = threadIdx.x; c < DM; c += blockDim.x) { float v = xr[c]; s += v * v; }
    __shared__ float red[32];
    #pragma unroll
    for (int o = 16; o; o >>= 1) s += __shfl_xor_sync(~0u, s, o);
    if ((threadIdx.x & 31) == 0) red[threadIdx.x >> 5] = s;
    __syncthreads();
    if (threadIdx.x < 32) {
        float v = (threadIdx.x < (blockDim.x >> 5)) ? red[threadIdx.x] : 0.0f;
        #pragma unroll
        for (int o = 16; o; o >>= 1) v += __shfl_xor_sync(~0u, v, o);
        if (threadIdx.x == 0) red[0] = v;
    }
    __syncthreads();
    float inv = rsqrtf(red[0] / (float)DM + 1e-5f);
    for (int c = threadIdx.x; c < DM; c += blockDim.x)
        out[row * DM + c] = xr[c] * inv * w[c];
}

// ---------------- causal depthwise conv1d (k=4) + bias + silu ----------------
__global__ void conv_silu_kernel(const float* __restrict__ cw, const float* __restrict__ cb) {
    int i = blockIdx.x * blockDim.x + threadIdx.x;
    int l = i >> 11, d = i & (DI - 1);
    float acc = cb[d];
    #pragma unroll
    for (int t = 0; t < 4; t++) {
        int ls = l - 3 + t;
        if (ls >= 0) acc = fmaf(cw[d * 4 + t], g_xr[ls * (2 * DI) + d], acc);
    }
    g_xp[i] = siluf(acc);
}

// ---------------- scan pass A: per-chunk carries (P, E) ----------------
__global__ void scanA_kernel(const float* __restrict__ A_log) {
    int t = blockIdx.x * blockDim.x + threadIdx.x;   // over SCH*NDN
    int c = t / NDN;
    int q = t - c * NDN;
    int d = q >> 4, n = q & 15;
    float A_dn = -expf(A_log[d * DS + n]);
    float h = 0.0f, P = 1.0f;
    int l0 = c * CL;
    for (int i = 0; i < CL; i++) {
        int l = l0 + i;
        float dl = g_delta[l * DI + d];
        float u  = g_xp[l * DI + d];
        float Bv = g_xdbl[l * XDBL + DTR + n];
        float dA = __expf(dl * A_dn);
        h = fmaf(dA, h, dl * u * Bv);
        P *= dA;
    }
    g_cp[t] = P;
    g_ce[t] = h;
}

// ---------------- scan combine: prefix the SCH carries per (d,n) ----------------
__global__ void scanC_kernel() {
    int q = blockIdx.x * blockDim.x + threadIdx.x;   // over NDN
    float H = 0.0f;
    #pragma unroll
    for (int c = 0; c < SCH; c++) {
        g_h0[c * NDN + q] = H;
        H = fmaf(g_cp[c * NDN + q], H, g_ce[c * NDN + q]);
    }
}

// ---------------- scan pass B: rescan chunk from true h0, write y ----------------
__global__ void scanB_kernel(const float* __restrict__ A_log, const float* __restrict__ Dp) {
    int t = blockIdx.x * blockDim.x + threadIdx.x;   // over SCH*NDN
    int c = t / NDN;
    int q = t - c * NDN;
    int d = q >> 4, n = q & 15;
    float A_dn = -expf(A_log[d * DS + n]);
    float Dv = Dp[d];
    float h = g_h0[c * NDN + q];
    int l0 = c * CL;
    for (int i = 0; i < CL; i++) {
        int l = l0 + i;
        float dl = g_delta[l * DI + d];
        float u  = g_xp[l * DI + d];
        float Bv = g_xdbl[l * XDBL + DTR + n];
        float Cv = g_xdbl[l * XDBL + DTR + DS + n];
        float dA = __expf(dl * A_dn);
        h = fmaf(dA, h, dl * u * Bv);
        float py = h * Cv;
        #pragma unroll
        for (int o = 8; o; o >>= 1) py += __shfl_xor_sync(~0u, py, o);
        if (n == 0) g_y[l * DI + d] = py + u * Dv;
    }
}

// ---------------- gate: y *= silu(res) ----------------
__global__ void gate_kernel() {
    int i = blockIdx.x * blockDim.x + threadIdx.x;
    int l = i >> 11, d = i & (DI - 1);
    g_y[i] = g_y[i] * siluf(g_xr[l * (2 * DI) + DI + d]);
}

// ================= FP16 mma.sync m16n8k16 NT GEMM, 128x128, double-buffered =================
// EPI: 0 = none, 1 = +bias then softplus, 2 = +residual.
// SWAP: 0 -> blockIdx.x = col tile; 1 -> blockIdx.x = row tile (B-tile reuse for huge N).
template <int EPI, int SWAP>
__global__ __launch_bounds__(256, 2)
void mma_nt(const float* __restrict__ A, int lda,
            const float* __restrict__ B, int ldb,
            float* __restrict__ C, int ldc,
            int N, int K, const float* __restrict__ resid,
            const float* __restrict__ bias) {
    __shared__ unsigned sA[2][8][32][4];
    __shared__ unsigned sB[2][16][32][2];

    const int tid  = threadIdx.x;
    const int lane = tid & 31;
    const int warp = tid >> 5;
    const int wm = warp & 1;
    const int wn = warp >> 1;
    const int rowBase = (SWAP ? blockIdx.x : blockIdx.y) * 128;
    const int colBase = (SWAP ? blockIdx.y : blockIdx.x) * 128;

    const int r0  = tid >> 2;
    const int kq  = tid & 3;
    const float* Arow0 = A + (long)(rowBase + r0) * lda + kq * 4;
    const float* Arow1 = A + (long)(rowBase + r0 + 64) * lda + kq * 4;
    const int nIdx0 = colBase + r0;
    const int nIdx1 = colBase + r0 + 64;
    const float* Brow0 = B + (long)nIdx0 * ldb + kq * 4;
    const float* Brow1 = B + (long)nIdx1 * ldb + kq * 4;
    const bool bv0 = nIdx0 < N;
    const bool bv1 = nIdx1 < N;

    float acc[4][4][4];
    #pragma unroll
    for (int i = 0; i < 4; i++)
        #pragma unroll
        for (int j = 0; j < 4; j++)
            #pragma unroll
            for (int q = 0; q < 4; q++) acc[i][j][q] = 0.0f;

    float4 ra[2], rb[2];
    auto ldg = [&](int k0) {
        ra[0] = *(const float4*)(Arow0 + k0);
        ra[1] = *(const float4*)(Arow1 + k0);
        rb[0] = bv0 ? *(const float4*)(Brow0 + k0) : make_float4(0.f,0.f,0.f,0.f);
        rb[1] = bv1 ? *(const float4*)(Brow1 + k0) : make_float4(0.f,0.f,0.f,0.f);
    };
    auto sts = [&](int st) {
        const int kcLo = (2 * kq) & 3;
        const int kcHi = (2 * kq + 1) & 3;
        const int kr   = kq >> 1;
        #pragma unroll
        for (int h = 0; h < 2; h++) {
            const int row = r0 + h * 64;
            const float4 va = ra[h];
            const float4 vb = rb[h];
            const int mt = row >> 4, rt = row & 15;
            const int lr = (rt & 7) << 2;
            const int rA = (rt >> 3) + 2 * kr;
            sA[st][mt][lr | kcLo][rA] = pkh2(va.x, va.y);
            sA[st][mt][lr | kcHi][rA] = pkh2(va.z, va.w);
            const int nt = row >> 3, ct = row & 7;
            const int lb = ct << 2;
            sB[st][nt][lb | kcLo][kr] = pkh2(vb.x, vb.y);
            sB[st][nt][lb | kcHi][kr] = pkh2(vb.z, vb.w);
        }
    };
    auto compute = [&](int st) {
        unsigned af[4][4];
        unsigned bf[4][2];
        #pragma unroll
        for (int i = 0; i < 4; i++) {
            uint4 v = *(const uint4*)&sA[st][wm * 4 + i][lane][0];
            af[i][0] = v.x; af[i][1] = v.y; af[i][2] = v.z; af[i][3] = v.w;
        }
        #pragma unroll
        for (int j = 0; j < 4; j++) {
            uint2 v = *(const uint2*)&sB[st][wn * 4 + j][lane][0];
            bf[j][0] = v.x; bf[j][1] = v.y;
        }
        #pragma unroll
        for (int i = 0; i < 4; i++)
            #pragma unroll
            for (int j = 0; j < 4; j++)
                mma_f16(acc[i][j], af[i], bf[j]);
    };

    ldg(0);
    sts(0);
    __syncthreads();
    int buf = 0;
    for (int k0 = 16; k0 < K; k0 += 16) {
        ldg(k0);
        compute(buf);
        sts(buf ^ 1);
        __syncthreads();
        buf ^= 1;
    }
    compute(buf);

    const int g   = lane >> 2;
    const int tig = lane & 3;
    #pragma unroll
    for (int i = 0; i < 4; i++) {
        const long row0 = rowBase + wm * 64 + i * 16 + g;
        #pragma unroll
        for (int j = 0; j < 4; j++) {
            const int col = colBase + wn * 32 + j * 8 + tig * 2;
            if (col < N) {
                float2 v01 = make_float2(acc[i][j][0], acc[i][j][1]);
                float2 v23 = make_float2(acc[i][j][2], acc[i][j][3]);
                if (EPI == 1) {
                    float b0 = bias[col], b1 = bias[col + 1];
                    v01.x = softplusf(v01.x + b0); v01.y = softplusf(v01.y + b1);
                    v23.x = softplusf(v23.x + b0); v23.y = softplusf(v23.y + b1);
                }
                if (EPI == 2) {
                    float2 t0 = *(const float2*)&resid[row0 * ldc + col];
                    float2 t1 = *(const float2*)&resid[(row0 + 8) * ldc + col];
                    v01.x += t0.x; v01.y += t0.y;
                    v23.x += t1.x; v23.y += t1.y;
                }
                *(float2*)&C[row0 * ldc + col]       = v01;
                *(float2*)&C[(row0 + 8) * ldc + col] = v23;
            }
        }
    }
}

// ---------------- fp32 NT SGEMM (split-K partials for x_proj; exact path) ----------------
__global__ __launch_bounds__(256, 2)
void sgemm_splitk(const float* __restrict__ A, int lda,
                  const float* __restrict__ B, int ldb,
                  float* __restrict__ C, int ldc,
                  int N, int K) {
    __shared__ float As[8][128];
    __shared__ float Bs[8][128];
    const int tid = threadIdx.x;
    const int rowBase = blockIdx.y * 128;
    const int colBase = blockIdx.x * 128;
    const int kOff = blockIdx.z * K;
    C += (size_t)blockIdx.z * PSTRIDE;

    const int aRow = tid >> 1;
    const int aCol = (tid & 1) << 2;
    const float* Aptr = A + (long)(rowBase + aRow) * lda + aCol + kOff;
    const bool bValid = (colBase + aRow) < N;
    const float* Bptr = B + (long)(colBase + aRow) * ldb + aCol + kOff;

    const int tr = (tid >> 4) << 3;
    const int tc = (tid & 15) << 3;

    float acc[8][8];
    #pragma unroll
    for (int i = 0; i < 8; i++)
        #pragma unroll
        for (int j = 0; j < 8; j++) acc[i][j] = 0.0f;

    for (int k0 = 0; k0 < K; k0 += 8) {
        float4 va = *(const float4*)(Aptr + k0);
        float4 vb = bValid ? *(const float4*)(Bptr + k0) : make_float4(0.f, 0.f, 0.f, 0.f);
        As[aCol + 0][aRow] = va.x; As[aCol + 1][aRow] = va.y;
        As[aCol + 2][aRow] = va.z; As[aCol + 3][aRow] = va.w;
        Bs[aCol + 0][aRow] = vb.x; Bs[aCol + 1][aRow] = vb.y;
        Bs[aCol + 2][aRow] = vb.z; Bs[aCol + 3][aRow] = vb.w;
        __syncthreads();
        #pragma unroll
        for (int kk = 0; kk < 8; kk++) {
            float rm[8], rn[8];
            *(float4*)(rm)     = *(const float4*)&As[kk][tr];
            *(float4*)(rm + 4) = *(const float4*)&As[kk][tr + 4];
            *(float4*)(rn)     = *(const float4*)&Bs[kk][tc];
            *(float4*)(rn + 4) = *(const float4*)&Bs[kk][tc + 4];
            #pragma unroll
            for (int i = 0; i < 8; i++)
                #pragma unroll
                for (int j = 0; j < 8; j++)
                    acc[i][j] = fmaf(rm[i], rn[j], acc[i][j]);
        }
        __syncthreads();
    }

    #pragma unroll
    for (int i = 0; i < 8; i++) {
        const long rr = rowBase + tr + i;
        #pragma unroll
        for (int j = 0; j < 8; j++) {
            const int c = colBase + tc + j;
            if (c < N) C[rr * ldc + c] = acc[i][j];
        }
    }
}

// ---------------- split-K reduction for x_proj ----------------
__global__ void splitk_reduce_kernel() {
    int i = blockIdx.x * blockDim.x + threadIdx.x;
    float s = 0.0f;
    #pragma unroll
    for (int p = 0; p < KSPL; p++) s += g_part[p * PSTRIDE + i];
    g_xdbl[i] = s;
}

// ---------------- host orchestration ----------------
extern "C" void kernel_launch(void* const* d_in, const int* in_sizes, int n_in,
                              void* d_out, int out_size) {
    const int*   ids        = (const int*)  d_in[0];
    const float* emb        = (const float*)d_in[1];
    const float* in_proj_w  = (const float*)d_in[2];
    const float* conv_w     = (const float*)d_in[3];
    const float* conv_b     = (const float*)d_in[4];
    const float* x_proj_w   = (const float*)d_in[5];
    const float* dt_proj_w  = (const float*)d_in[6];
    const float* dt_proj_b  = (const float*)d_in[7];
    const float* A_log      = (const float*)d_in[8];
    const float* D_param    = (const float*)d_in[9];
    const float* out_proj_w = (const float*)d_in[10];
    const float* norm_w     = (const float*)d_in[11];
    const float* norm_f_w   = (const float*)d_in[12];
    float* out = (float*)d_out;

    float *x, *xn, *xr, *xp, *xdbl, *delta, *y, *part;
    cudaGetSymbolAddress((void**)&x,     g_x);
    cudaGetSymbolAddress((void**)&xn,    g_xn);
    cudaGetSymbolAddress((void**)&xr,    g_xr);
    cudaGetSymbolAddress((void**)&xp,    g_xp);
    cudaGetSymbolAddress((void**)&xdbl,  g_xdbl);
    cudaGetSymbolAddress((void**)&delta, g_delta);
    cudaGetSymbolAddress((void**)&y,     g_y);
    cudaGetSymbolAddress((void**)&part,  g_part);

    embed_kernel<<<(LSEQ * DM) / 256, 256>>>(ids, emb);

    for (int layer = 0; layer < 2; layer++) {
        rmsnorm_kernel<<<LSEQ, 256>>>(x, norm_w + layer * DM, xn);

        // x_and_res = xn @ in_proj_w^T : [2048, 4096]   (fp16 mma 128x128)
        mma_nt<0, 0><<<dim3((2 * DI) / 128, LSEQ / 128), 256>>>(
            xn, DM, in_proj_w + (size_t)layer * 2 * DI * DM, DM,
            xr, 2 * DI, 2 * DI, DM, (const float*)0, (const float*)0);

        conv_silu_kernel<<<(LSEQ * DI) / 256, 256>>>(
            conv_w + (size_t)layer * DI * 4, conv_b + (size_t)layer * DI);

        // x_dbl = xp @ x_proj_w^T : [2048, 96]  (fp32 split-K: 16 chunks of 128)
        sgemm_splitk<<<dim3(1, LSEQ / 128, KSPL), 256>>>(
            xp, DI, x_proj_w + (size_t)layer * XDBL * DI, DI,
            part, XDBL, XDBL, DI / KSPL);
        splitk_reduce_kernel<<<(LSEQ * XDBL) / 256, 256>>>();

        // delta = softplus(x_dbl[:, :64] @ dt_proj_w^T + b) : [2048, 2048]  (fp16 mma, K=64)
        mma_nt<1, 0><<<dim3(DI / 128, LSEQ / 128), 256>>>(
            xdbl, XDBL, dt_proj_w + (size_t)layer * DI * DTR, DTR,
            delta, DI, DI, DTR, (const float*)0, dt_proj_b + (size_t)layer * DI);

        // chunked two-pass scan
        scanA_kernel<<<(SCH * NDN) / 256, 256>>>(A_log + (size_t)layer * DI * DS);
        scanC_kernel<<<NDN / 256, 256>>>();
        scanB_kernel<<<(SCH * NDN) / 256, 256>>>(
            A_log + (size_t)layer * DI * DS, D_param + (size_t)layer * DI);
        gate_kernel<<<(LSEQ * DI) / 256, 256>>>();

        // x = x + ygated @ out_proj_w^T : [2048, 1024]   (fp16 mma 128x128)
        mma_nt<2, 0><<<dim3(DM / 128, LSEQ / 128), 256>>>(
            y, DI, out_proj_w + (size_t)layer * DM * DI, DI,
            x, DM, DM, DI, x, (const float*)0);
    }

    rmsnorm_kernel<<<LSEQ, 256>>>(x, norm_f_w, xn);

    // logits = xf @ embedding^T : [2048, 50264]  (fp16 mma; row tiles fastest -> B-tile L2 reuse)
    mma_nt<0, 1><<<dim3(LSEQ / 128, (VOC + 127) / 128), 256>>>(
        xn, DM, emb, DM, out, VOC, VOC, DM, (const float*)0, (const float*)0);
}